// round 1
// baseline (speedup 1.0000x reference)
#include <cuda_runtime.h>

// ---------------------------------------------------------------------------
// DGLGNN node kernel: 2-layer MLP encoders + 3 bidirectional GCN layers with
// LayerNorm + residual, JK-concat output of net nodes.
//
// Strategy:
//   * degrees + CSR (in-edges / out-edges) built per launch (graph-capturable)
//   * generic fp32 tiled GEMM (64x64x16, 4x4 microtile) for all dense matmuls
//   * GEMM epilogue (mode 1) directly produces y = dinv*relu(x) message rows
//     and s = relu(x+root)/deg self-loop rows
//   * aggregation kernel: warp-per-node CSR gather (no atomics) + fused
//     LayerNorm + leaky-relu + residual + output write
// ---------------------------------------------------------------------------

#define DD 128
#define MAXN 50048
#define MAXE 800000

// ------------------------- static device scratch ---------------------------
__device__ float g_h[MAXN * DD];          // current node features
__device__ float g_t[40000 * 256];        // encoder temp (largest stage)
__device__ float g_yf[MAXN * DD];         // dinv_in  * relu(xf)
__device__ float g_yr[MAXN * DD];         // dinv_out * relu(xr)
__device__ float g_sf[MAXN * DD];         // relu(xf+rootf)/deg_in
__device__ float g_sr[MAXN * DD];         // relu(xr+rootr)/deg_out
__device__ int   g_cnt_in[MAXN], g_cnt_out[MAXN];
__device__ int   g_rp_in[MAXN + 1], g_rp_out[MAXN + 1];
__device__ int   g_cur_in[MAXN], g_cur_out[MAXN];
__device__ int   g_colin[MAXE], g_colout[MAXE];
__device__ float g_dinv_in[MAXN], g_dinv_out[MAXN];
__device__ float g_invdeg_in[MAXN], g_invdeg_out[MAXN];

// ------------------------------- graph prep --------------------------------
__global__ void zero_cnt_k(int n) {
    int i = blockIdx.x * blockDim.x + threadIdx.x;
    if (i < n) { g_cnt_in[i] = 0; g_cnt_out[i] = 0; }
}

__global__ void hist_k(const int* __restrict__ src, const int* __restrict__ dst, int e_cnt) {
    int e = blockIdx.x * blockDim.x + threadIdx.x;
    if (e < e_cnt) {
        atomicAdd(&g_cnt_in[dst[e]], 1);
        atomicAdd(&g_cnt_out[src[e]], 1);
    }
}

__global__ void deg_k(int n) {
    int i = blockIdx.x * blockDim.x + threadIdx.x;
    if (i < n) {
        float di = (float)g_cnt_in[i] + 1.0f;
        float dо = (float)g_cnt_out[i] + 1.0f;
        g_dinv_in[i]   = rsqrtf(di);
        g_dinv_out[i]  = rsqrtf(dо);
        g_invdeg_in[i] = 1.0f / di;
        g_invdeg_out[i] = 1.0f / dо;
    }
}

// one block per array (gridDim.x == 2), serial chunked Hillis-Steele scan
__global__ void scan_k(int n) {
    const int* cnt = (blockIdx.x == 0) ? g_cnt_in : g_cnt_out;
    int* rp  = (blockIdx.x == 0) ? g_rp_in  : g_rp_out;
    int* cur = (blockIdx.x == 0) ? g_cur_in : g_cur_out;
    __shared__ int tmp[1024];
    __shared__ int carry;
    int tid = threadIdx.x;
    if (tid == 0) carry = 0;
    __syncthreads();
    for (int base = 0; base < n; base += 1024) {
        int i = base + tid;
        int v = (i < n) ? cnt[i] : 0;
        tmp[tid] = v;
        __syncthreads();
        for (int off = 1; off < 1024; off <<= 1) {
            int t = (tid >= off) ? tmp[tid - off] : 0;
            __syncthreads();
            tmp[tid] += t;
            __syncthreads();
        }
        int c = carry;
        int excl = c + tmp[tid] - v;
        if (i < n) { rp[i] = excl; cur[i] = excl; }
        __syncthreads();
        if (tid == 0) carry = c + tmp[1023];
        __syncthreads();
    }
    if (tid == 0) rp[n] = carry;
}

__global__ void scatter_k(const int* __restrict__ src, const int* __restrict__ dst, int e_cnt) {
    int e = blockIdx.x * blockDim.x + threadIdx.x;
    if (e < e_cnt) {
        int s = src[e], d = dst[e];
        int p = atomicAdd(&g_cur_in[d], 1);
        g_colin[p] = s;
        int q = atomicAdd(&g_cur_out[s], 1);
        g_colout[q] = d;
    }
}

// --------------------------------- GEMM ------------------------------------
// C[M,Nc] = A[M,K] @ W[Nc,K]^T + bias
// mode 0: Y[r*ldY + c] = lrelu(x)
// mode 1: Y[r*ldY + c] = dinv[r]*relu(x);  S[r*ldY+c] = relu(x+root[c])*invdeg[r]
// Requires Nc % 64 == 0 (guaranteed here: 128 or 256); M guarded; K guarded.
__global__ __launch_bounds__(256) void gemm_k(
    const float* __restrict__ A, int M, int K,
    const float* __restrict__ W, const float* __restrict__ bias,
    float* __restrict__ Y, int ldY, int mode,
    float* __restrict__ S,
    const float* __restrict__ dinv, const float* __restrict__ invdeg,
    const float* __restrict__ root)
{
    __shared__ __align__(16) float As[16][72];
    __shared__ __align__(16) float Ws[16][72];
    const int brow = blockIdx.x * 64;
    const int bcol = blockIdx.y * 64;
    const int tid = threadIdx.x;
    const int tx = tid & 15, ty = tid >> 4;
    float acc[4][4] = {};

    for (int k0 = 0; k0 < K; k0 += 16) {
#pragma unroll
        for (int i = 0; i < 4; i++) {
            int flat = tid + i * 256;
            int k = flat & 15, m = flat >> 4;
            int gr = brow + m, gk = k0 + k;
            As[k][m] = (gr < M && gk < K) ? A[(size_t)gr * K + gk] : 0.0f;
            int gc = bcol + m;
            Ws[k][m] = (gk < K) ? W[(size_t)gc * K + gk] : 0.0f;
        }
        __syncthreads();
#pragma unroll
        for (int k = 0; k < 16; k++) {
            float4 a = *reinterpret_cast<const float4*>(&As[k][ty << 2]);
            float4 w = *reinterpret_cast<const float4*>(&Ws[k][tx << 2]);
            acc[0][0] += a.x * w.x; acc[0][1] += a.x * w.y; acc[0][2] += a.x * w.z; acc[0][3] += a.x * w.w;
            acc[1][0] += a.y * w.x; acc[1][1] += a.y * w.y; acc[1][2] += a.y * w.z; acc[1][3] += a.y * w.w;
            acc[2][0] += a.z * w.x; acc[2][1] += a.z * w.y; acc[2][2] += a.z * w.z; acc[2][3] += a.z * w.w;
            acc[3][0] += a.w * w.x; acc[3][1] += a.w * w.y; acc[3][2] += a.w * w.z; acc[3][3] += a.w * w.w;
        }
        __syncthreads();
    }

#pragma unroll
    for (int im = 0; im < 4; im++) {
        int r = brow + (ty << 2) + im;
        if (r >= M) continue;
        float dv = 0.f, idg = 0.f;
        if (mode == 1) { dv = dinv[r]; idg = invdeg[r]; }
#pragma unroll
        for (int jn = 0; jn < 4; jn++) {
            int c = bcol + (tx << 2) + jn;
            float x = acc[im][jn] + bias[c];
            if (mode == 0) {
                Y[(size_t)r * ldY + c] = (x >= 0.f) ? x : 0.1f * x;
            } else {
                Y[(size_t)r * ldY + c] = dv * fmaxf(x, 0.f);
                S[(size_t)r * ldY + c] = fmaxf(x + root[c], 0.f) * idg;
            }
        }
    }
}

// ----------------------- aggregation + LN + residual -----------------------
__global__ __launch_bounds__(256) void agg_k(
    int n, int n_inst,
    const float* __restrict__ lng, const float* __restrict__ lnb,
    float* __restrict__ out, int out_col0)
{
    int wid  = (blockIdx.x * blockDim.x + threadIdx.x) >> 5;
    int lane = threadIdx.x & 31;
    if (wid >= n) return;

    const float4* yf4 = reinterpret_cast<const float4*>(g_yf);
    const float4* yr4 = reinterpret_cast<const float4*>(g_yr);
    const float4* sf4 = reinterpret_cast<const float4*>(g_sf);
    const float4* sr4 = reinterpret_cast<const float4*>(g_sr);

    float4 af = make_float4(0.f, 0.f, 0.f, 0.f);
    float4 ar = make_float4(0.f, 0.f, 0.f, 0.f);

    int b0 = g_rp_in[wid], b1 = g_rp_in[wid + 1];
    for (int e = b0; e < b1; e++) {
        int s = g_colin[e];
        float4 v = yf4[(size_t)s * 32 + lane];
        af.x += v.x; af.y += v.y; af.z += v.z; af.w += v.w;
    }
    int c0 = g_rp_out[wid], c1 = g_rp_out[wid + 1];
    for (int e = c0; e < c1; e++) {
        int d = g_colout[e];
        float4 v = yr4[(size_t)d * 32 + lane];
        ar.x += v.x; ar.y += v.y; ar.z += v.z; ar.w += v.w;
    }

    float di = g_dinv_in[wid], dou = g_dinv_out[wid];
    float4 sA = sf4[(size_t)wid * 32 + lane];
    float4 sB = sr4[(size_t)wid * 32 + lane];
    float4 s;
    s.x = sA.x + sB.x + di * af.x + dou * ar.x;
    s.y = sA.y + sB.y + di * af.y + dou * ar.y;
    s.z = sA.z + sB.z + di * af.z + dou * ar.z;
    s.w = sA.w + sB.w + di * af.w + dou * ar.w;

    float sum = s.x + s.y + s.z + s.w;
    float sq  = s.x * s.x + s.y * s.y + s.z * s.z + s.w * s.w;
#pragma unroll
    for (int o = 16; o > 0; o >>= 1) {
        sum += __shfl_xor_sync(0xffffffffu, sum, o);
        sq  += __shfl_xor_sync(0xffffffffu, sq, o);
    }
    float mu   = sum * (1.0f / 128.0f);
    float var  = sq * (1.0f / 128.0f) - mu * mu;
    float rstd = rsqrtf(var + 1e-5f);

    float4 g  = reinterpret_cast<const float4*>(lng)[lane];
    float4 bb = reinterpret_cast<const float4*>(lnb)[lane];
    float4 ho = reinterpret_cast<const float4*>(g_h)[(size_t)wid * 32 + lane];

    float4 hn;
    {
        float v;
        v = (s.x - mu) * rstd * g.x + bb.x; v = (v >= 0.f) ? v : 0.1f * v; hn.x = v + ho.x;
        v = (s.y - mu) * rstd * g.y + bb.y; v = (v >= 0.f) ? v : 0.1f * v; hn.y = v + ho.y;
        v = (s.z - mu) * rstd * g.z + bb.z; v = (v >= 0.f) ? v : 0.1f * v; hn.z = v + ho.z;
        v = (s.w - mu) * rstd * g.w + bb.w; v = (v >= 0.f) ? v : 0.1f * v; hn.w = v + ho.w;
    }
    reinterpret_cast<float4*>(g_h)[(size_t)wid * 32 + lane] = hn;

    if (wid >= n_inst) {
        float4* o4 = reinterpret_cast<float4*>(out + (size_t)(wid - n_inst) * 512 + out_col0);
        o4[lane] = hn;
    }
}

__global__ void copy_h0_k(int n_inst, int n_net, float* __restrict__ out) {
    int i = blockIdx.x * blockDim.x + threadIdx.x;
    int total = n_net * DD;
    if (i < total) {
        int node = i >> 7, c = i & 127;
        out[(size_t)node * 512 + c] = g_h[((size_t)(n_inst + node)) * DD + c];
    }
}

// --------------------------------- launch ----------------------------------
extern "C" void kernel_launch(void* const* d_in, const int* in_sizes, int n_in,
                              void* d_out, int out_size)
{
    const float* x        = (const float*)d_in[0];
    const float* x_net    = (const float*)d_in[1];
    const float* enc_W1   = (const float*)d_in[2];
    const float* enc_b1   = (const float*)d_in[3];
    const float* enc_W2   = (const float*)d_in[4];
    const float* enc_b2   = (const float*)d_in[5];
    const float* encn_W1  = (const float*)d_in[6];
    const float* encn_b1  = (const float*)d_in[7];
    const float* encn_W2  = (const float*)d_in[8];
    const float* encn_b2  = (const float*)d_in[9];
    const float* conv_W   = (const float*)d_in[10];
    const float* conv_b   = (const float*)d_in[11];
    const float* conv_root = (const float*)d_in[12];
    const float* rconv_W  = (const float*)d_in[13];
    const float* rconv_b  = (const float*)d_in[14];
    const float* rconv_root = (const float*)d_in[15];
    const float* ln_g     = (const float*)d_in[16];
    const float* ln_b     = (const float*)d_in[17];
    const int*   src      = (const int*)d_in[18];
    const int*   dst      = (const int*)d_in[19];

    const int NI = in_sizes[0] / 11;
    const int NN = in_sizes[1] / 3;
    const int Nn = NI + NN;
    const int E_ = in_sizes[18];
    float* out = (float*)d_out;

    // device addresses of scratch symbols
    float *gh, *gt, *gyf, *gyr, *gsf, *gsr, *gdi, *gdo, *gii, *gio;
    cudaGetSymbolAddress((void**)&gh,  g_h);
    cudaGetSymbolAddress((void**)&gt,  g_t);
    cudaGetSymbolAddress((void**)&gyf, g_yf);
    cudaGetSymbolAddress((void**)&gyr, g_yr);
    cudaGetSymbolAddress((void**)&gsf, g_sf);
    cudaGetSymbolAddress((void**)&gsr, g_sr);
    cudaGetSymbolAddress((void**)&gdi, g_dinv_in);
    cudaGetSymbolAddress((void**)&gdo, g_dinv_out);
    cudaGetSymbolAddress((void**)&gii, g_invdeg_in);
    cudaGetSymbolAddress((void**)&gio, g_invdeg_out);

    // ---- graph prep: degrees + CSR ----
    zero_cnt_k<<<(Nn + 255) / 256, 256>>>(Nn);
    hist_k<<<(E_ + 255) / 256, 256>>>(src, dst, E_);
    deg_k<<<(Nn + 255) / 256, 256>>>(Nn);
    scan_k<<<2, 1024>>>(Nn);
    scatter_k<<<(E_ + 255) / 256, 256>>>(src, dst, E_);

    // ---- encoders ----
    // instance: [NI,11] -> 256 -> 128
    gemm_k<<<dim3((NI + 63) / 64, 4), 256>>>(x, NI, 11, enc_W1, enc_b1,
                                             gt, 256, 0, nullptr, nullptr, nullptr, nullptr);
    gemm_k<<<dim3((NI + 63) / 64, 2), 256>>>(gt, NI, 256, enc_W2, enc_b2,
                                             gh, 128, 0, nullptr, nullptr, nullptr, nullptr);
    // net: [NN,3] -> 128 -> 128
    gemm_k<<<dim3((NN + 63) / 64, 2), 256>>>(x_net, NN, 3, encn_W1, encn_b1,
                                             gt, 128, 0, nullptr, nullptr, nullptr, nullptr);
    gemm_k<<<dim3((NN + 63) / 64, 2), 256>>>(gt, NN, 128, encn_W2, encn_b2,
                                             gh + (size_t)NI * DD, 128, 0,
                                             nullptr, nullptr, nullptr, nullptr);
    // h0 of net nodes -> output cols [0,128)
    copy_h0_k<<<(NN * DD + 255) / 256, 256>>>(NI, NN, out);

    // ---- 3 GCN layers ----
    for (int l = 0; l < 3; l++) {
        const float* Wf = conv_W  + (size_t)l * DD * DD;
        const float* Wr = rconv_W + (size_t)l * DD * DD;
        gemm_k<<<dim3((Nn + 63) / 64, 2), 256>>>(gh, Nn, DD, Wf, conv_b + l * DD,
                                                 gyf, 128, 1, gsf, gdi, gii,
                                                 conv_root + l * DD);
        gemm_k<<<dim3((Nn + 63) / 64, 2), 256>>>(gh, Nn, DD, Wr, rconv_b + l * DD,
                                                 gyr, 128, 1, gsr, gdo, gio,
                                                 rconv_root + l * DD);
        agg_k<<<(Nn * 32 + 255) / 256, 256>>>(Nn, NI, ln_g + l * DD, ln_b + l * DD,
                                              out, (l + 1) * DD);
    }
}

// round 3
// speedup vs baseline: 1.1136x; 1.1136x over previous
#include <cuda_runtime.h>

// ---------------------------------------------------------------------------
// DGLGNN node kernel: 2-layer MLP encoders + 3 bidirectional GCN layers with
// LayerNorm + residual, JK-concat output of net nodes.
//
// R1/R2 changes vs R0:
//   * serial 2-block scan (82.8us) -> 3-phase parallel scan (~6us)
//   * fp32 GEMM inner loop -> packed fma.rn.f32x2 (2 FMAs/issue slot)
//   * forward+reverse layer GEMMs fused into one launch (gridDim.z = 2)
// ---------------------------------------------------------------------------

#define DD 128
#define MAXN 50048
#define MAXE 800000
#define SCANB 1024
#define MAXBLK 64

// ------------------------- static device scratch ---------------------------
__device__ float g_h[MAXN * DD];          // current node features
__device__ float g_t[40000 * 256];        // encoder temp (largest stage)
__device__ float g_yf[MAXN * DD];         // dinv_in  * relu(xf)
__device__ float g_yr[MAXN * DD];         // dinv_out * relu(xr)
__device__ float g_sf[MAXN * DD];         // relu(xf+rootf)/deg_in
__device__ float g_sr[MAXN * DD];         // relu(xr+rootr)/deg_out
__device__ int   g_cnt_in[MAXN], g_cnt_out[MAXN];
__device__ int   g_rp_in[MAXN + 1], g_rp_out[MAXN + 1];
__device__ int   g_cur_in[MAXN], g_cur_out[MAXN];
__device__ int   g_colin[MAXE], g_colout[MAXE];
__device__ float g_dinv_in[MAXN], g_dinv_out[MAXN];
__device__ float g_invdeg_in[MAXN], g_invdeg_out[MAXN];
__device__ int   g_bsum[2][MAXBLK];
__device__ int   g_boff[2][MAXBLK];

// --------------------------- f32x2 helpers ---------------------------------
__device__ __forceinline__ unsigned long long pk2(float lo, float hi) {
    unsigned long long r;
    asm("mov.b64 %0, {%1, %2};" : "=l"(r) : "f"(lo), "f"(hi));
    return r;
}
__device__ __forceinline__ void upk2(unsigned long long v, float& lo, float& hi) {
    asm("mov.b64 {%0, %1}, %2;" : "=f"(lo), "=f"(hi) : "l"(v));
}
__device__ __forceinline__ void fma2(unsigned long long& d, unsigned long long a,
                                     unsigned long long b) {
    asm("fma.rn.f32x2 %0, %1, %2, %0;" : "+l"(d) : "l"(a), "l"(b));
}

// ------------------------------- graph prep --------------------------------
__global__ void zero_cnt_k(int n) {
    int i = blockIdx.x * blockDim.x + threadIdx.x;
    if (i < n) { g_cnt_in[i] = 0; g_cnt_out[i] = 0; }
}

__global__ void hist_k(const int* __restrict__ src, const int* __restrict__ dst, int e_cnt) {
    int e = blockIdx.x * blockDim.x + threadIdx.x;
    if (e < e_cnt) {
        atomicAdd(&g_cnt_in[dst[e]], 1);
        atomicAdd(&g_cnt_out[src[e]], 1);
    }
}

__global__ void deg_k(int n) {
    int i = blockIdx.x * blockDim.x + threadIdx.x;
    if (i < n) {
        float di = (float)g_cnt_in[i] + 1.0f;
        float dO = (float)g_cnt_out[i] + 1.0f;
        g_dinv_in[i]    = rsqrtf(di);
        g_dinv_out[i]   = rsqrtf(dO);
        g_invdeg_in[i]  = 1.0f / di;
        g_invdeg_out[i] = 1.0f / dO;
    }
}

// phase 1: per-block inclusive scan of 1024-chunks; write local exclusive
__global__ __launch_bounds__(SCANB) void scan1_k(int n) {
    int arr = blockIdx.y;
    const int* cnt = arr == 0 ? g_cnt_in : g_cnt_out;
    int* rp  = arr == 0 ? g_rp_in  : g_rp_out;
    int* cur = arr == 0 ? g_cur_in : g_cur_out;
    __shared__ int tmp[SCANB];
    int tid = threadIdx.x;
    int i = blockIdx.x * SCANB + tid;
    int v = (i < n) ? cnt[i] : 0;
    tmp[tid] = v;
    __syncthreads();
#pragma unroll
    for (int off = 1; off < SCANB; off <<= 1) {
        int t = (tid >= off) ? tmp[tid - off] : 0;
        __syncthreads();
        tmp[tid] += t;
        __syncthreads();
    }
    int incl = tmp[tid];
    if (i < n) { rp[i] = incl - v; cur[i] = incl - v; }
    if (tid == SCANB - 1) g_bsum[arr][blockIdx.x] = incl;
}

// phase 2: scan the (<=64) block sums; one block per array
__global__ void scan2_k(int nb, int n) {
    int arr = blockIdx.x;
    __shared__ int tmp[MAXBLK];
    int tid = threadIdx.x;
    int v = (tid < nb) ? g_bsum[arr][tid] : 0;
    tmp[tid] = v;
    __syncthreads();
#pragma unroll
    for (int off = 1; off < MAXBLK; off <<= 1) {
        int t = (tid >= off) ? tmp[tid - off] : 0;
        __syncthreads();
        tmp[tid] += t;
        __syncthreads();
    }
    g_boff[arr][tid] = tmp[tid] - v;
    if (tid == MAXBLK - 1) {
        int* rp = arr == 0 ? g_rp_in : g_rp_out;
        rp[n] = tmp[MAXBLK - 1];
    }
}

// phase 3: add block offsets
__global__ __launch_bounds__(SCANB) void scan3_k(int n) {
    int arr = blockIdx.y;
    int* rp  = arr == 0 ? g_rp_in  : g_rp_out;
    int* cur = arr == 0 ? g_cur_in : g_cur_out;
    int off = g_boff[arr][blockIdx.x];
    int i = blockIdx.x * SCANB + threadIdx.x;
    if (i < n) { rp[i] += off; cur[i] += off; }
}

__global__ void scatter_k(const int* __restrict__ src, const int* __restrict__ dst, int e_cnt) {
    int e = blockIdx.x * blockDim.x + threadIdx.x;
    if (e < e_cnt) {
        int s = src[e], d = dst[e];
        int p = atomicAdd(&g_cur_in[d], 1);
        g_colin[p] = s;
        int q = atomicAdd(&g_cur_out[s], 1);
        g_colout[q] = d;
    }
}

// --------------------------------- GEMM ------------------------------------
// C[M,Nc] = A[M,K] @ W[Nc,K]^T + bias
// mode 0: Y[r*ldY + c] = lrelu(x)
// mode 1: Y[r*ldY + c] = dinv[r]*relu(x);  S[r*ldY+c] = relu(x+root[c])*invdeg[r]
// Inner product uses packed fma.rn.f32x2: each issue does 2 FMAs.
__global__ __launch_bounds__(256) void gemm_k(
    const float* __restrict__ A, int M, int K,
    const float* __restrict__ W, const float* __restrict__ bias,
    float* __restrict__ Y, int ldY, int mode,
    float* __restrict__ S,
    const float* __restrict__ dinv, const float* __restrict__ invdeg,
    const float* __restrict__ root)
{
    __shared__ __align__(16) float As[16][72];
    __shared__ __align__(16) float Ws[16][72];
    const int brow = blockIdx.x * 64;
    const int bcol = blockIdx.y * 64;
    const int tid = threadIdx.x;
    const int tx = tid & 15, ty = tid >> 4;
    unsigned long long acc[4][2];
#pragma unroll
    for (int i = 0; i < 4; i++) { acc[i][0] = 0ull; acc[i][1] = 0ull; }

    for (int k0 = 0; k0 < K; k0 += 16) {
#pragma unroll
        for (int i = 0; i < 4; i++) {
            int flat = tid + i * 256;
            int k = flat & 15, m = flat >> 4;
            int gr = brow + m, gk = k0 + k;
            As[k][m] = (gr < M && gk < K) ? A[(size_t)gr * K + gk] : 0.0f;
            int gc = bcol + m;
            Ws[k][m] = (gk < K) ? W[(size_t)gc * K + gk] : 0.0f;
        }
        __syncthreads();
#pragma unroll
        for (int k = 0; k < 16; k++) {
            float4 a = *reinterpret_cast<const float4*>(&As[k][ty << 2]);
            float4 w = *reinterpret_cast<const float4*>(&Ws[k][tx << 2]);
            unsigned long long w01 = pk2(w.x, w.y);
            unsigned long long w23 = pk2(w.z, w.w);
            unsigned long long a0 = pk2(a.x, a.x);
            unsigned long long a1 = pk2(a.y, a.y);
            unsigned long long a2 = pk2(a.z, a.z);
            unsigned long long a3 = pk2(a.w, a.w);
            fma2(acc[0][0], a0, w01); fma2(acc[0][1], a0, w23);
            fma2(acc[1][0], a1, w01); fma2(acc[1][1], a1, w23);
            fma2(acc[2][0], a2, w01); fma2(acc[2][1], a2, w23);
            fma2(acc[3][0], a3, w01); fma2(acc[3][1], a3, w23);
        }
        __syncthreads();
    }

#pragma unroll
    for (int im = 0; im < 4; im++) {
        int r = brow + (ty << 2) + im;
        if (r >= M) continue;
        float dv = 0.f, idg = 0.f;
        if (mode == 1) { dv = dinv[r]; idg = invdeg[r]; }
        float c0, c1, c2, c3;
        upk2(acc[im][0], c0, c1);
        upk2(acc[im][1], c2, c3);
        float cc[4] = {c0, c1, c2, c3};
#pragma unroll
        for (int jn = 0; jn < 4; jn++) {
            int c = bcol + (tx << 2) + jn;
            float x = cc[jn] + bias[c];
            if (mode == 0) {
                Y[(size_t)r * ldY + c] = (x >= 0.f) ? x : 0.1f * x;
            } else {
                Y[(size_t)r * ldY + c] = dv * fmaxf(x, 0.f);
                S[(size_t)r * ldY + c] = fmaxf(x + root[c], 0.f) * idg;
            }
        }
    }
}

// fused fwd+rev layer GEMM: blockIdx.z selects direction (0=fwd, 1=rev)
__global__ __launch_bounds__(256) void gemm_layer_k(
    const float* __restrict__ A, int M,
    const float* __restrict__ Wf, const float* __restrict__ bf, const float* __restrict__ rootf,
    const float* __restrict__ Wr, const float* __restrict__ br, const float* __restrict__ rootr)
{
    const int K = DD;
    const int rev = blockIdx.z;
    const float* W    = rev ? Wr : Wf;
    const float* bias = rev ? br : bf;
    const float* root = rev ? rootr : rootf;
    float* Y = rev ? g_yr : g_yf;
    float* S = rev ? g_sr : g_sf;
    const float* dinv   = rev ? g_dinv_out   : g_dinv_in;
    const float* invdeg = rev ? g_invdeg_out : g_invdeg_in;

    __shared__ __align__(16) float As[16][72];
    __shared__ __align__(16) float Ws[16][72];
    const int brow = blockIdx.x * 64;
    const int bcol = blockIdx.y * 64;
    const int tid = threadIdx.x;
    const int tx = tid & 15, ty = tid >> 4;
    unsigned long long acc[4][2];
#pragma unroll
    for (int i = 0; i < 4; i++) { acc[i][0] = 0ull; acc[i][1] = 0ull; }

    for (int k0 = 0; k0 < K; k0 += 16) {
#pragma unroll
        for (int i = 0; i < 4; i++) {
            int flat = tid + i * 256;
            int k = flat & 15, m = flat >> 4;
            int gr = brow + m, gk = k0 + k;
            As[k][m] = (gr < M) ? A[(size_t)gr * K + gk] : 0.0f;
            int gc = bcol + m;
            Ws[k][m] = W[(size_t)gc * K + gk];
        }
        __syncthreads();
#pragma unroll
        for (int k = 0; k < 16; k++) {
            float4 a = *reinterpret_cast<const float4*>(&As[k][ty << 2]);
            float4 w = *reinterpret_cast<const float4*>(&Ws[k][tx << 2]);
            unsigned long long w01 = pk2(w.x, w.y);
            unsigned long long w23 = pk2(w.z, w.w);
            unsigned long long a0 = pk2(a.x, a.x);
            unsigned long long a1 = pk2(a.y, a.y);
            unsigned long long a2 = pk2(a.z, a.z);
            unsigned long long a3 = pk2(a.w, a.w);
            fma2(acc[0][0], a0, w01); fma2(acc[0][1], a0, w23);
            fma2(acc[1][0], a1, w01); fma2(acc[1][1], a1, w23);
            fma2(acc[2][0], a2, w01); fma2(acc[2][1], a2, w23);
            fma2(acc[3][0], a3, w01); fma2(acc[3][1], a3, w23);
        }
        __syncthreads();
    }

#pragma unroll
    for (int im = 0; im < 4; im++) {
        int r = brow + (ty << 2) + im;
        if (r >= M) continue;
        float dv = dinv[r], idg = invdeg[r];
        float c0, c1, c2, c3;
        upk2(acc[im][0], c0, c1);
        upk2(acc[im][1], c2, c3);
        float cc[4] = {c0, c1, c2, c3};
#pragma unroll
        for (int jn = 0; jn < 4; jn++) {
            int c = bcol + (tx << 2) + jn;
            float x = cc[jn] + bias[c];
            Y[(size_t)r * DD + c] = dv * fmaxf(x, 0.f);
            S[(size_t)r * DD + c] = fmaxf(x + root[c], 0.f) * idg;
        }
    }
}

// ----------------------- aggregation + LN + residual -----------------------
__global__ __launch_bounds__(256) void agg_k(
    int n, int n_inst,
    const float* __restrict__ lng, const float* __restrict__ lnb,
    float* __restrict__ out, int out_col0)
{
    int wid  = (blockIdx.x * blockDim.x + threadIdx.x) >> 5;
    int lane = threadIdx.x & 31;
    if (wid >= n) return;

    const float4* yf4 = reinterpret_cast<const float4*>(g_yf);
    const float4* yr4 = reinterpret_cast<const float4*>(g_yr);
    const float4* sf4 = reinterpret_cast<const float4*>(g_sf);
    const float4* sr4 = reinterpret_cast<const float4*>(g_sr);

    float4 af = make_float4(0.f, 0.f, 0.f, 0.f);
    float4 ar = make_float4(0.f, 0.f, 0.f, 0.f);

    int b0 = g_rp_in[wid], b1 = g_rp_in[wid + 1];
    for (int e = b0; e < b1; e++) {
        int s = g_colin[e];
        float4 v = yf4[(size_t)s * 32 + lane];
        af.x += v.x; af.y += v.y; af.z += v.z; af.w += v.w;
    }
    int c0 = g_rp_out[wid], c1 = g_rp_out[wid + 1];
    for (int e = c0; e < c1; e++) {
        int d = g_colout[e];
        float4 v = yr4[(size_t)d * 32 + lane];
        ar.x += v.x; ar.y += v.y; ar.z += v.z; ar.w += v.w;
    }

    float di = g_dinv_in[wid], dou = g_dinv_out[wid];
    float4 sA = sf4[(size_t)wid * 32 + lane];
    float4 sB = sr4[(size_t)wid * 32 + lane];
    float4 s;
    s.x = sA.x + sB.x + di * af.x + dou * ar.x;
    s.y = sA.y + sB.y + di * af.y + dou * ar.y;
    s.z = sA.z + sB.z + di * af.z + dou * ar.z;
    s.w = sA.w + sB.w + di * af.w + dou * ar.w;

    float sum = s.x + s.y + s.z + s.w;
    float sq  = s.x * s.x + s.y * s.y + s.z * s.z + s.w * s.w;
#pragma unroll
    for (int o = 16; o > 0; o >>= 1) {
        sum += __shfl_xor_sync(0xffffffffu, sum, o);
        sq  += __shfl_xor_sync(0xffffffffu, sq, o);
    }
    float mu   = sum * (1.0f / 128.0f);
    float var  = sq * (1.0f / 128.0f) - mu * mu;
    float rstd = rsqrtf(var + 1e-5f);

    float4 g  = reinterpret_cast<const float4*>(lng)[lane];
    float4 bb = reinterpret_cast<const float4*>(lnb)[lane];
    float4 ho = reinterpret_cast<const float4*>(g_h)[(size_t)wid * 32 + lane];

    float4 hn;
    {
        float v;
        v = (s.x - mu) * rstd * g.x + bb.x; v = (v >= 0.f) ? v : 0.1f * v; hn.x = v + ho.x;
        v = (s.y - mu) * rstd * g.y + bb.y; v = (v >= 0.f) ? v : 0.1f * v; hn.y = v + ho.y;
        v = (s.z - mu) * rstd * g.z + bb.z; v = (v >= 0.f) ? v : 0.1f * v; hn.z = v + ho.z;
        v = (s.w - mu) * rstd * g.w + bb.w; v = (v >= 0.f) ? v : 0.1f * v; hn.w = v + ho.w;
    }
    reinterpret_cast<float4*>(g_h)[(size_t)wid * 32 + lane] = hn;

    if (wid >= n_inst) {
        float4* o4 = reinterpret_cast<float4*>(out + (size_t)(wid - n_inst) * 512 + out_col0);
        o4[lane] = hn;
    }
}

__global__ void copy_h0_k(int n_inst, int n_net, float* __restrict__ out) {
    int i = blockIdx.x * blockDim.x + threadIdx.x;
    int total = n_net * DD;
    if (i < total) {
        int node = i >> 7, c = i & 127;
        out[(size_t)node * 512 + c] = g_h[((size_t)(n_inst + node)) * DD + c];
    }
}

// --------------------------------- launch ----------------------------------
extern "C" void kernel_launch(void* const* d_in, const int* in_sizes, int n_in,
                              void* d_out, int out_size)
{
    const float* x        = (const float*)d_in[0];
    const float* x_net    = (const float*)d_in[1];
    const float* enc_W1   = (const float*)d_in[2];
    const float* enc_b1   = (const float*)d_in[3];
    const float* enc_W2   = (const float*)d_in[4];
    const float* enc_b2   = (const float*)d_in[5];
    const float* encn_W1  = (const float*)d_in[6];
    const float* encn_b1  = (const float*)d_in[7];
    const float* encn_W2  = (const float*)d_in[8];
    const float* encn_b2  = (const float*)d_in[9];
    const float* conv_W   = (const float*)d_in[10];
    const float* conv_b   = (const float*)d_in[11];
    const float* conv_root = (const float*)d_in[12];
    const float* rconv_W  = (const float*)d_in[13];
    const float* rconv_b  = (const float*)d_in[14];
    const float* rconv_root = (const float*)d_in[15];
    const float* ln_g     = (const float*)d_in[16];
    const float* ln_b     = (const float*)d_in[17];
    const int*   src      = (const int*)d_in[18];
    const int*   dst      = (const int*)d_in[19];

    const int NI = in_sizes[0] / 11;
    const int NN = in_sizes[1] / 3;
    const int Nn = NI + NN;
    const int E_ = in_sizes[18];
    float* out = (float*)d_out;

    float *gh, *gt;
    cudaGetSymbolAddress((void**)&gh,  g_h);
    cudaGetSymbolAddress((void**)&gt,  g_t);

    const int nb = (Nn + SCANB - 1) / SCANB;   // <= MAXBLK

    // ---- graph prep: degrees + CSR ----
    zero_cnt_k<<<(Nn + 255) / 256, 256>>>(Nn);
    hist_k<<<(E_ + 255) / 256, 256>>>(src, dst, E_);
    deg_k<<<(Nn + 255) / 256, 256>>>(Nn);
    scan1_k<<<dim3(nb, 2), SCANB>>>(Nn);
    scan2_k<<<2, MAXBLK>>>(nb, Nn);
    scan3_k<<<dim3(nb, 2), SCANB>>>(Nn);
    scatter_k<<<(E_ + 255) / 256, 256>>>(src, dst, E_);

    // ---- encoders ----
    gemm_k<<<dim3((NI + 63) / 64, 4), 256>>>(x, NI, 11, enc_W1, enc_b1,
                                             gt, 256, 0, nullptr, nullptr, nullptr, nullptr);
    gemm_k<<<dim3((NI + 63) / 64, 2), 256>>>(gt, NI, 256, enc_W2, enc_b2,
                                             gh, 128, 0, nullptr, nullptr, nullptr, nullptr);
    gemm_k<<<dim3((NN + 63) / 64, 2), 256>>>(x_net, NN, 3, encn_W1, encn_b1,
                                             gt, 128, 0, nullptr, nullptr, nullptr, nullptr);
    gemm_k<<<dim3((NN + 63) / 64, 2), 256>>>(gt, NN, 128, encn_W2, encn_b2,
                                             gh + (size_t)NI * DD, 128, 0,
                                             nullptr, nullptr, nullptr, nullptr);
    copy_h0_k<<<(NN * DD + 255) / 256, 256>>>(NI, NN, out);

    // ---- 3 GCN layers ----
    for (int l = 0; l < 3; l++) {
        gemm_layer_k<<<dim3((Nn + 63) / 64, 2, 2), 256>>>(
            gh, Nn,
            conv_W  + (size_t)l * DD * DD, conv_b  + l * DD, conv_root  + l * DD,
            rconv_W + (size_t)l * DD * DD, rconv_b + l * DD, rconv_root + l * DD);
        agg_k<<<(Nn * 32 + 255) / 256, 256>>>(Nn, NI, ln_g + l * DD, ln_b + l * DD,
                                              out, (l + 1) * DD);
    }
}

// round 8
// speedup vs baseline: 1.2098x; 1.0864x over previous
#include <cuda_runtime.h>

// ---------------------------------------------------------------------------
// DGLGNN node kernel: 2-layer MLP encoders + 3 bidirectional GCN layers with
// LayerNorm + residual, JK-concat output of net nodes.
//
// R4 kernel, fifth submission (four prior rounds hit broker
// GPUAcquisitionTimeout before any measurement):
// main GEMMs (layers + enc2/encn2) on a 128x128-tile kernel with 8x8
// microtile and packed fma.rn.f32x2; W-operand pairs read pre-packed from
// SMEM (ulonglong2), amortizing A-duplication MOVs 8:64.
// ---------------------------------------------------------------------------

#define DD 128
#define MAXN 50048
#define MAXE 800000
#define SCANB 1024
#define MAXBLK 64

// ------------------------- static device scratch ---------------------------
__device__ float g_h[MAXN * DD];          // current node features
__device__ float g_t[40000 * 256];        // encoder temp (largest stage)
__device__ float g_yf[MAXN * DD];         // dinv_in  * relu(xf)
__device__ float g_yr[MAXN * DD];         // dinv_out * relu(xr)
__device__ float g_sf[MAXN * DD];         // relu(xf+rootf)/deg_in
__device__ float g_sr[MAXN * DD];         // relu(xr+rootr)/deg_out
__device__ int   g_cnt_in[MAXN], g_cnt_out[MAXN];
__device__ int   g_rp_in[MAXN + 1], g_rp_out[MAXN + 1];
__device__ int   g_cur_in[MAXN], g_cur_out[MAXN];
__device__ int   g_colin[MAXE], g_colout[MAXE];
__device__ float g_dinv_in[MAXN], g_dinv_out[MAXN];
__device__ float g_invdeg_in[MAXN], g_invdeg_out[MAXN];
__device__ int   g_bsum[2][MAXBLK];
__device__ int   g_boff[2][MAXBLK];

// --------------------------- f32x2 helpers ---------------------------------
__device__ __forceinline__ unsigned long long pk2(float lo, float hi) {
    unsigned long long r;
    asm("mov.b64 %0, {%1, %2};" : "=l"(r) : "f"(lo), "f"(hi));
    return r;
}
__device__ __forceinline__ void upk2(unsigned long long v, float& lo, float& hi) {
    asm("mov.b64 {%0, %1}, %2;" : "=f"(lo), "=f"(hi) : "l"(v));
}
__device__ __forceinline__ void fma2(unsigned long long& d, unsigned long long a,
                                     unsigned long long b) {
    asm("fma.rn.f32x2 %0, %1, %2, %0;" : "+l"(d) : "l"(a), "l"(b));
}

// ------------------------------- graph prep --------------------------------
__global__ void zero_cnt_k(int n) {
    int i = blockIdx.x * blockDim.x + threadIdx.x;
    if (i < n) { g_cnt_in[i] = 0; g_cnt_out[i] = 0; }
}

__global__ void hist_k(const int* __restrict__ src, const int* __restrict__ dst, int e_cnt) {
    int e = blockIdx.x * blockDim.x + threadIdx.x;
    if (e < e_cnt) {
        atomicAdd(&g_cnt_in[dst[e]], 1);
        atomicAdd(&g_cnt_out[src[e]], 1);
    }
}

__global__ void deg_k(int n) {
    int i = blockIdx.x * blockDim.x + threadIdx.x;
    if (i < n) {
        float di = (float)g_cnt_in[i] + 1.0f;
        float dO = (float)g_cnt_out[i] + 1.0f;
        g_dinv_in[i]    = rsqrtf(di);
        g_dinv_out[i]   = rsqrtf(dO);
        g_invdeg_in[i]  = 1.0f / di;
        g_invdeg_out[i] = 1.0f / dO;
    }
}

// phase 1: per-block inclusive scan of 1024-chunks; write local exclusive
__global__ __launch_bounds__(SCANB) void scan1_k(int n) {
    int arr = blockIdx.y;
    const int* cnt = arr == 0 ? g_cnt_in : g_cnt_out;
    int* rp  = arr == 0 ? g_rp_in  : g_rp_out;
    int* cur = arr == 0 ? g_cur_in : g_cur_out;
    __shared__ int tmp[SCANB];
    int tid = threadIdx.x;
    int i = blockIdx.x * SCANB + tid;
    int v = (i < n) ? cnt[i] : 0;
    tmp[tid] = v;
    __syncthreads();
#pragma unroll
    for (int off = 1; off < SCANB; off <<= 1) {
        int t = (tid >= off) ? tmp[tid - off] : 0;
        __syncthreads();
        tmp[tid] += t;
        __syncthreads();
    }
    int incl = tmp[tid];
    if (i < n) { rp[i] = incl - v; cur[i] = incl - v; }
    if (tid == SCANB - 1) g_bsum[arr][blockIdx.x] = incl;
}

// phase 2: scan the (<=64) block sums; one block per array
__global__ void scan2_k(int nb, int n) {
    int arr = blockIdx.x;
    __shared__ int tmp[MAXBLK];
    int tid = threadIdx.x;
    int v = (tid < nb) ? g_bsum[arr][tid] : 0;
    tmp[tid] = v;
    __syncthreads();
#pragma unroll
    for (int off = 1; off < MAXBLK; off <<= 1) {
        int t = (tid >= off) ? tmp[tid - off] : 0;
        __syncthreads();
        tmp[tid] += t;
        __syncthreads();
    }
    g_boff[arr][tid] = tmp[tid] - v;
    if (tid == MAXBLK - 1) {
        int* rp = arr == 0 ? g_rp_in : g_rp_out;
        rp[n] = tmp[MAXBLK - 1];
    }
}

// phase 3: add block offsets
__global__ __launch_bounds__(SCANB) void scan3_k(int n) {
    int arr = blockIdx.y;
    int* rp  = arr == 0 ? g_rp_in  : g_rp_out;
    int* cur = arr == 0 ? g_cur_in : g_cur_out;
    int off = g_boff[arr][blockIdx.x];
    int i = blockIdx.x * SCANB + threadIdx.x;
    if (i < n) { rp[i] += off; cur[i] += off; }
}

__global__ void scatter_k(const int* __restrict__ src, const int* __restrict__ dst, int e_cnt) {
    int e = blockIdx.x * blockDim.x + threadIdx.x;
    if (e < e_cnt) {
        int s = src[e], d = dst[e];
        int p = atomicAdd(&g_cur_in[d], 1);
        g_colin[p] = s;
        int q = atomicAdd(&g_cur_out[s], 1);
        g_colout[q] = d;
    }
}

// ---------------------- generic small GEMM (encoders-1) --------------------
// C[M,Nc] = A[M,K] @ W[Nc,K]^T + bias, lrelu epilogue
__global__ __launch_bounds__(256) void gemm_k(
    const float* __restrict__ A, int M, int K,
    const float* __restrict__ W, const float* __restrict__ bias,
    float* __restrict__ Y, int ldY)
{
    __shared__ __align__(16) float As[16][72];
    __shared__ __align__(16) float Ws[16][72];
    const int brow = blockIdx.x * 64;
    const int bcol = blockIdx.y * 64;
    const int tid = threadIdx.x;
    const int tx = tid & 15, ty = tid >> 4;
    float acc[4][4] = {};

    for (int k0 = 0; k0 < K; k0 += 16) {
#pragma unroll
        for (int i = 0; i < 4; i++) {
            int flat = tid + i * 256;
            int k = flat & 15, m = flat >> 4;
            int gr = brow + m, gk = k0 + k;
            As[k][m] = (gr < M && gk < K) ? A[(size_t)gr * K + gk] : 0.0f;
            int gc = bcol + m;
            Ws[k][m] = (gk < K) ? W[(size_t)gc * K + gk] : 0.0f;
        }
        __syncthreads();
#pragma unroll
        for (int k = 0; k < 16; k++) {
            float4 a = *reinterpret_cast<const float4*>(&As[k][ty << 2]);
            float4 w = *reinterpret_cast<const float4*>(&Ws[k][tx << 2]);
            acc[0][0] += a.x * w.x; acc[0][1] += a.x * w.y; acc[0][2] += a.x * w.z; acc[0][3] += a.x * w.w;
            acc[1][0] += a.y * w.x; acc[1][1] += a.y * w.y; acc[1][2] += a.y * w.z; acc[1][3] += a.y * w.w;
            acc[2][0] += a.z * w.x; acc[2][1] += a.z * w.y; acc[2][2] += a.z * w.z; acc[2][3] += a.z * w.w;
            acc[3][0] += a.w * w.x; acc[3][1] += a.w * w.y; acc[3][2] += a.w * w.z; acc[3][3] += a.w * w.w;
        }
        __syncthreads();
    }

#pragma unroll
    for (int im = 0; im < 4; im++) {
        int r = brow + (ty << 2) + im;
        if (r >= M) continue;
#pragma unroll
        for (int jn = 0; jn < 4; jn++) {
            int c = bcol + (tx << 2) + jn;
            float x = acc[im][jn] + bias[c];
            Y[(size_t)r * ldY + c] = (x >= 0.f) ? x : 0.1f * x;
        }
    }
}

// ------------------- 128x128-tile FFMA2 GEMM (N=128 fixed) -----------------
// C[M,128] = A[M,K] @ W[128,K]^T, K % 16 == 0.
// mode 0: Y0[r*128+c] = lrelu(x + bias)            (gridDim.z == 1)
// mode 1: blockIdx.z selects fwd(0)/rev(1); writes g_y*/g_s* epilogues.
__global__ __launch_bounds__(256, 2) void gemm128_k(
    const float* __restrict__ A, int M, int K,
    const float* __restrict__ Wf, const float* __restrict__ bf, const float* __restrict__ rootf,
    const float* __restrict__ Wr, const float* __restrict__ br, const float* __restrict__ rootr,
    float* __restrict__ Y0, int mode)
{
    __shared__ __align__(16) float As[16][136];
    __shared__ __align__(16) float Ws[16][136];

    const int rev = (mode == 1) ? blockIdx.z : 0;
    const float* W    = rev ? Wr : Wf;
    const float* bias = rev ? br : bf;
    const float* root = rev ? rootr : rootf;

    const int brow = blockIdx.x * 128;
    const int tid = threadIdx.x;
    const int tx = tid & 15;     // col group (8 cols)
    const int ty = tid >> 4;     // row group (8 rows)

    unsigned long long acc[8][4];
#pragma unroll
    for (int i = 0; i < 8; i++)
#pragma unroll
        for (int j = 0; j < 4; j++) acc[i][j] = 0ull;

    for (int k0 = 0; k0 < K; k0 += 16) {
        // load A tile [128 rows x 16 k] (transposed into As[k][row])
#pragma unroll
        for (int it = 0; it < 2; it++) {
            int idx = tid + it * 256;           // 0..511 float4 slots
            int row = idx >> 2;
            int c4  = (idx & 3) << 2;
            int gr = brow + row;
            float4 v = make_float4(0.f, 0.f, 0.f, 0.f);
            if (gr < M) v = *reinterpret_cast<const float4*>(&A[(size_t)gr * K + k0 + c4]);
            As[c4 + 0][row] = v.x;
            As[c4 + 1][row] = v.y;
            As[c4 + 2][row] = v.z;
            As[c4 + 3][row] = v.w;
        }
        // load W tile [128 cols x 16 k]
#pragma unroll
        for (int it = 0; it < 2; it++) {
            int idx = tid + it * 256;
            int row = idx >> 2;
            int c4  = (idx & 3) << 2;
            float4 v = *reinterpret_cast<const float4*>(&W[(size_t)row * K + k0 + c4]);
            Ws[c4 + 0][row] = v.x;
            Ws[c4 + 1][row] = v.y;
            Ws[c4 + 2][row] = v.z;
            Ws[c4 + 3][row] = v.w;
        }
        __syncthreads();
#pragma unroll
        for (int k = 0; k < 16; k++) {
            const ulonglong2 w01 = *reinterpret_cast<const ulonglong2*>(&Ws[k][tx << 3]);
            const ulonglong2 w23 = *reinterpret_cast<const ulonglong2*>(&Ws[k][(tx << 3) + 4]);
            const float4 aA = *reinterpret_cast<const float4*>(&As[k][ty << 3]);
            const float4 aB = *reinterpret_cast<const float4*>(&As[k][(ty << 3) + 4]);
            float av[8] = {aA.x, aA.y, aA.z, aA.w, aB.x, aB.y, aB.z, aB.w};
#pragma unroll
            for (int i = 0; i < 8; i++) {
                unsigned long long ad = pk2(av[i], av[i]);
                fma2(acc[i][0], ad, w01.x);
                fma2(acc[i][1], ad, w01.y);
                fma2(acc[i][2], ad, w23.x);
                fma2(acc[i][3], ad, w23.y);
            }
        }
        __syncthreads();
    }

    const int c0 = tx << 3;
    float4 bA = *reinterpret_cast<const float4*>(&bias[c0]);
    float4 bB = *reinterpret_cast<const float4*>(&bias[c0 + 4]);
    float bv[8] = {bA.x, bA.y, bA.z, bA.w, bB.x, bB.y, bB.z, bB.w};

    if (mode == 0) {
#pragma unroll
        for (int i = 0; i < 8; i++) {
            int r = brow + (ty << 3) + i;
            if (r >= M) continue;
            float cc[8];
#pragma unroll
            for (int j = 0; j < 4; j++) upk2(acc[i][j], cc[2 * j], cc[2 * j + 1]);
            float o[8];
#pragma unroll
            for (int j = 0; j < 8; j++) {
                float x = cc[j] + bv[j];
                o[j] = (x >= 0.f) ? x : 0.1f * x;
            }
            float4* yp = reinterpret_cast<float4*>(&Y0[(size_t)r * 128 + c0]);
            yp[0] = make_float4(o[0], o[1], o[2], o[3]);
            yp[1] = make_float4(o[4], o[5], o[6], o[7]);
        }
    } else {
        float* Yd = rev ? g_yr : g_yf;
        float* Sd = rev ? g_sr : g_sf;
        const float* dinv   = rev ? g_dinv_out   : g_dinv_in;
        const float* invdeg = rev ? g_invdeg_out : g_invdeg_in;
        float4 rA = *reinterpret_cast<const float4*>(&root[c0]);
        float4 rB = *reinterpret_cast<const float4*>(&root[c0 + 4]);
        float rv[8] = {rA.x, rA.y, rA.z, rA.w, rB.x, rB.y, rB.z, rB.w};
#pragma unroll
        for (int i = 0; i < 8; i++) {
            int r = brow + (ty << 3) + i;
            if (r >= M) continue;
            float dv = dinv[r], idg = invdeg[r];
            float cc[8];
#pragma unroll
            for (int j = 0; j < 4; j++) upk2(acc[i][j], cc[2 * j], cc[2 * j + 1]);
            float yv[8], sv[8];
#pragma unroll
            for (int j = 0; j < 8; j++) {
                float x = cc[j] + bv[j];
                yv[j] = dv * fmaxf(x, 0.f);
                sv[j] = fmaxf(x + rv[j], 0.f) * idg;
            }
            float4* yp = reinterpret_cast<float4*>(&Yd[(size_t)r * 128 + c0]);
            yp[0] = make_float4(yv[0], yv[1], yv[2], yv[3]);
            yp[1] = make_float4(yv[4], yv[5], yv[6], yv[7]);
            float4* sp = reinterpret_cast<float4*>(&Sd[(size_t)r * 128 + c0]);
            sp[0] = make_float4(sv[0], sv[1], sv[2], sv[3]);
            sp[1] = make_float4(sv[4], sv[5], sv[6], sv[7]);
        }
    }
}

// ----------------------- aggregation + LN + residual -----------------------
__global__ __launch_bounds__(256) void agg_k(
    int n, int n_inst,
    const float* __restrict__ lng, const float* __restrict__ lnb,
    float* __restrict__ out, int out_col0)
{
    int wid  = (blockIdx.x * blockDim.x + threadIdx.x) >> 5;
    int lane = threadIdx.x & 31;
    if (wid >= n) return;

    const float4* yf4 = reinterpret_cast<const float4*>(g_yf);
    const float4* yr4 = reinterpret_cast<const float4*>(g_yr);
    const float4* sf4 = reinterpret_cast<const float4*>(g_sf);
    const float4* sr4 = reinterpret_cast<const float4*>(g_sr);

    float4 af = make_float4(0.f, 0.f, 0.f, 0.f);
    float4 ar = make_float4(0.f, 0.f, 0.f, 0.f);

    int b0 = g_rp_in[wid], b1 = g_rp_in[wid + 1];
    for (int e = b0; e < b1; e++) {
        int s = g_colin[e];
        float4 v = yf4[(size_t)s * 32 + lane];
        af.x += v.x; af.y += v.y; af.z += v.z; af.w += v.w;
    }
    int c0 = g_rp_out[wid], c1 = g_rp_out[wid + 1];
    for (int e = c0; e < c1; e++) {
        int d = g_colout[e];
        float4 v = yr4[(size_t)d * 32 + lane];
        ar.x += v.x; ar.y += v.y; ar.z += v.z; ar.w += v.w;
    }

    float di = g_dinv_in[wid], dou = g_dinv_out[wid];
    float4 sA = sf4[(size_t)wid * 32 + lane];
    float4 sB = sr4[(size_t)wid * 32 + lane];
    float4 s;
    s.x = sA.x + sB.x + di * af.x + dou * ar.x;
    s.y = sA.y + sB.y + di * af.y + dou * ar.y;
    s.z = sA.z + sB.z + di * af.z + dou * ar.z;
    s.w = sA.w + sB.w + di * af.w + dou * ar.w;

    float sum = s.x + s.y + s.z + s.w;
    float sq  = s.x * s.x + s.y * s.y + s.z * s.z + s.w * s.w;
#pragma unroll
    for (int o = 16; o > 0; o >>= 1) {
        sum += __shfl_xor_sync(0xffffffffu, sum, o);
        sq  += __shfl_xor_sync(0xffffffffu, sq, o);
    }
    float mu   = sum * (1.0f / 128.0f);
    float var  = sq * (1.0f / 128.0f) - mu * mu;
    float rstd = rsqrtf(var + 1e-5f);

    float4 g  = reinterpret_cast<const float4*>(lng)[lane];
    float4 bb = reinterpret_cast<const float4*>(lnb)[lane];
    float4 ho = reinterpret_cast<const float4*>(g_h)[(size_t)wid * 32 + lane];

    float4 hn;
    {
        float v;
        v = (s.x - mu) * rstd * g.x + bb.x; v = (v >= 0.f) ? v : 0.1f * v; hn.x = v + ho.x;
        v = (s.y - mu) * rstd * g.y + bb.y; v = (v >= 0.f) ? v : 0.1f * v; hn.y = v + ho.y;
        v = (s.z - mu) * rstd * g.z + bb.z; v = (v >= 0.f) ? v : 0.1f * v; hn.z = v + ho.z;
        v = (s.w - mu) * rstd * g.w + bb.w; v = (v >= 0.f) ? v : 0.1f * v; hn.w = v + ho.w;
    }
    reinterpret_cast<float4*>(g_h)[(size_t)wid * 32 + lane] = hn;

    if (wid >= n_inst) {
        float4* o4 = reinterpret_cast<float4*>(out + (size_t)(wid - n_inst) * 512 + out_col0);
        o4[lane] = hn;
    }
}

__global__ void copy_h0_k(int n_inst, int n_net, float* __restrict__ out) {
    int i = blockIdx.x * blockDim.x + threadIdx.x;
    int total = n_net * DD;
    if (i < total) {
        int node = i >> 7, c = i & 127;
        out[(size_t)node * 512 + c] = g_h[((size_t)(n_inst + node)) * DD + c];
    }
}

// --------------------------------- launch ----------------------------------
extern "C" void kernel_launch(void* const* d_in, const int* in_sizes, int n_in,
                              void* d_out, int out_size)
{
    const float* x        = (const float*)d_in[0];
    const float* x_net    = (const float*)d_in[1];
    const float* enc_W1   = (const float*)d_in[2];
    const float* enc_b1   = (const float*)d_in[3];
    const float* enc_W2   = (const float*)d_in[4];
    const float* enc_b2   = (const float*)d_in[5];
    const float* encn_W1  = (const float*)d_in[6];
    const float* encn_b1  = (const float*)d_in[7];
    const float* encn_W2  = (const float*)d_in[8];
    const float* encn_b2  = (const float*)d_in[9];
    const float* conv_W   = (const float*)d_in[10];
    const float* conv_b   = (const float*)d_in[11];
    const float* conv_root = (const float*)d_in[12];
    const float* rconv_W  = (const float*)d_in[13];
    const float* rconv_b  = (const float*)d_in[14];
    const float* rconv_root = (const float*)d_in[15];
    const float* ln_g     = (const float*)d_in[16];
    const float* ln_b     = (const float*)d_in[17];
    const int*   src      = (const int*)d_in[18];
    const int*   dst      = (const int*)d_in[19];

    const int NI = in_sizes[0] / 11;
    const int NN = in_sizes[1] / 3;
    const int Nn = NI + NN;
    const int E_ = in_sizes[18];
    float* out = (float*)d_out;

    float *gh, *gt;
    cudaGetSymbolAddress((void**)&gh,  g_h);
    cudaGetSymbolAddress((void**)&gt,  g_t);

    const int nb = (Nn + SCANB - 1) / SCANB;   // <= MAXBLK

    // ---- graph prep: degrees + CSR ----
    zero_cnt_k<<<(Nn + 255) / 256, 256>>>(Nn);
    hist_k<<<(E_ + 255) / 256, 256>>>(src, dst, E_);
    deg_k<<<(Nn + 255) / 256, 256>>>(Nn);
    scan1_k<<<dim3(nb, 2), SCANB>>>(Nn);
    scan2_k<<<2, MAXBLK>>>(nb, Nn);
    scan3_k<<<dim3(nb, 2), SCANB>>>(Nn);
    scatter_k<<<(E_ + 255) / 256, 256>>>(src, dst, E_);

    // ---- encoders ----
    // enc1: [NI,11] -> 256  (small-K generic kernel)
    gemm_k<<<dim3((NI + 63) / 64, 4), 256>>>(x, NI, 11, enc_W1, enc_b1, gt, 256);
    // enc2: [NI,256] -> 128 (big tile kernel, mode 0)
    gemm128_k<<<dim3((NI + 127) / 128, 1, 1), 256>>>(gt, NI, 256,
        enc_W2, enc_b2, nullptr, nullptr, nullptr, nullptr, gh, 0);
    // encn1: [NN,3] -> 128
    gemm_k<<<dim3((NN + 63) / 64, 2), 256>>>(x_net, NN, 3, encn_W1, encn_b1, gt, 128);
    // encn2: [NN,128] -> 128
    gemm128_k<<<dim3((NN + 127) / 128, 1, 1), 256>>>(gt, NN, 128,
        encn_W2, encn_b2, nullptr, nullptr, nullptr, nullptr,
        gh + (size_t)NI * DD, 0);
    copy_h0_k<<<(NN * DD + 255) / 256, 256>>>(NI, NN, out);

    // ---- 3 GCN layers ----
    for (int l = 0; l < 3; l++) {
        gemm128_k<<<dim3((Nn + 127) / 128, 1, 2), 256>>>(
            gh, Nn, 128,
            conv_W  + (size_t)l * DD * DD, conv_b  + l * DD, conv_root  + l * DD,
            rconv_W + (size_t)l * DD * DD, rconv_b + l * DD, rconv_root + l * DD,
            nullptr, 1);
        agg_k<<<(Nn * 32 + 255) / 256, 256>>>(Nn, NI, ln_g + l * DD, ln_b + l * DD,
                                              out, (l + 1) * DD);
    }
}